// round 14
// baseline (speedup 1.0000x reference)
#include <cuda_runtime.h>
#include <cuda_fp16.h>
#include <cstdint>

// B=2, H=16, S=2048, D=64 fp32 attention; out = [context | weights].
// prep_k/prep_v: K -> fp16 natural, V -> fp16 transposed [d][s].
// prep_m: mask int32 -> bitpacked (536 MB -> 16.8 MB).
// Pass 1: flash-style (no online max), fp16 m16n8k16 mma, bit-mask from regs,
//         fp16 unnormalized weights to scratch (.cs).
// Pass 2: w_fp32 = fp16_w * rinv.

#define SDIM    2048
#define DDIM    64
#define BHN     32
#define TQ      128
#define WQ      16
#define CK      64
#define NCH     32
#define KSTRH   88      // halfs; bank = (12*grp+tig) mod 32, bijective
#define VSTRH   88
#define THREADS 256
#define SCALE   0.125f

// bytes: K 2*64*88*2 = 22528 | V 22528  -> 45056 B
#define SMEM_BYTES (22528 + 22528)

__device__ float    g_ri[BHN * SDIM];
__device__ __half   g_Kh [(size_t)BHN * SDIM * DDIM];
__device__ __half   g_Vt [(size_t)BHN * DDIM * SDIM];
__device__ __half   g_W16[(size_t)BHN * SDIM * SDIM];    // 268 MB scratch
__device__ uint64_t g_Mp [(size_t)BHN * SDIM * (SDIM / 64)];  // 16.8 MB packed mask

__device__ __forceinline__ uint32_t f22h(float x, float y) {
    __half2 h = __floats2half2_rn(x, y);
    return *(uint32_t*)&h;
}

__device__ __forceinline__ void mma_f16(float c[4],
    uint32_t a0, uint32_t a1, uint32_t a2, uint32_t a3,
    uint32_t b0, uint32_t b1)
{
    asm volatile(
        "mma.sync.aligned.m16n8k16.row.col.f32.f16.f16.f32 "
        "{%0,%1,%2,%3}, {%4,%5,%6,%7}, {%8,%9}, {%0,%1,%2,%3};"
        : "+f"(c[0]), "+f"(c[1]), "+f"(c[2]), "+f"(c[3])
        : "r"(a0), "r"(a1), "r"(a2), "r"(a3), "r"(b0), "r"(b1));
}

__device__ __forceinline__ void cp16(void* dst_smem, const void* src) {
    uint32_t d = (uint32_t)__cvta_generic_to_shared(dst_smem);
    asm volatile("cp.async.cg.shared.global [%0], [%1], 16;" :: "r"(d), "l"(src));
}
__device__ __forceinline__ void stg_cs32(__half* p, uint32_t v) {
    asm volatile("st.global.cs.u32 [%0], %1;" :: "l"(p), "r"(v) : "memory");
}
#define CP_COMMIT()  asm volatile("cp.async.commit_group;" ::: "memory")
#define CP_WAIT0()   asm volatile("cp.async.wait_group 0;" ::: "memory")

// ---- prep: K fp32 -> fp16 natural ----
__global__ __launch_bounds__(256)
void prep_k(const float* __restrict__ K)
{
    size_t i = ((size_t)blockIdx.x * 256 + threadIdx.x) * 4;
    float4 v = *(const float4*)(K + i);
    __half2* o = (__half2*)(g_Kh + i);
    o[0] = __floats2half2_rn(v.x, v.y);
    o[1] = __floats2half2_rn(v.z, v.w);
}

// ---- prep: V fp32 [s][d] -> fp16 transposed [d][s] ----
__global__ __launch_bounds__(256)
void prep_v(const float* __restrict__ V)
{
    __shared__ float tile[64][65];
    const int bh = blockIdx.y, s0 = blockIdx.x * 64;
    const float* Vb = V + ((size_t)bh * SDIM + s0) * DDIM;
    const int t = threadIdx.x;
#pragma unroll
    for (int j = 0; j < 4; j++) {
        int i = t + 256 * j, r = i >> 4, c4 = i & 15;
        float4 v = *(const float4*)(Vb + (size_t)r * DDIM + c4 * 4);
        tile[r][c4 * 4 + 0] = v.x; tile[r][c4 * 4 + 1] = v.y;
        tile[r][c4 * 4 + 2] = v.z; tile[r][c4 * 4 + 3] = v.w;
    }
    __syncthreads();
    const int d = t >> 2, sb = (t & 3) * 16;
    __half2* o = (__half2*)(g_Vt + ((size_t)bh * DDIM + d) * SDIM + s0 + sb);
#pragma unroll
    for (int k = 0; k < 8; k++)
        o[k] = __floats2half2_rn(tile[sb + 2 * k][d], tile[sb + 2 * k + 1][d]);
}

// ---- prep: mask int32 -> bitpacked uint64 (bit k = key k masked) ----
__global__ __launch_bounds__(256)
void prep_m(const int* __restrict__ M)
{
    const int gw   = ((int)blockIdx.x * 256 + (int)threadIdx.x) >> 5;  // 0..16383
    const int lane = threadIdx.x & 31;
#pragma unroll
    for (int r = 0; r < 4; r++) {
        const int row = gw * 4 + r;
        const int* mr = M + (size_t)row * SDIM;
        uint64_t* out = g_Mp + (size_t)row * 32;
#pragma unroll 4
        for (int c = 0; c < 32; c++) {
            int v0 = mr[c * 64 + lane];
            int v1 = mr[c * 64 + 32 + lane];
            uint32_t b0 = __ballot_sync(0xffffffffu, v0 != 0);
            uint32_t b1 = __ballot_sync(0xffffffffu, v1 != 0);
            if (lane == 0) out[c] = (uint64_t)b0 | ((uint64_t)b1 << 32);
        }
    }
}

__global__ __launch_bounds__(THREADS, 2)
void attn_pass1(const float* __restrict__ Q, float* __restrict__ ctx)
{
    extern __shared__ __half smh[];
    __half* Ksm = smh;                        // [2][64 x 88]
    __half* Vsm = smh + 2 * 64 * KSTRH;       // [2][64 x 88]

    const int t    = threadIdx.x;
    const int w    = t >> 5;
    const int lane = t & 31;
    const int grp  = lane >> 2;
    const int tig  = lane & 3;
    const int bh   = blockIdx.y;
    const int qw   = blockIdx.x * TQ + w * WQ;

    const __half* KhB = g_Kh + (size_t)bh * SDIM * DDIM;
    const __half* VtB = g_Vt + (size_t)bh * DDIM * SDIM;
    const float* Qw = Q + ((size_t)bh * SDIM + qw) * DDIM;
    const uint64_t* Mp0 = g_Mp + ((size_t)bh * SDIM + qw + grp) * 32;
    const uint64_t* Mp1 = Mp0 + 8 * 32;
    float*  Cw  = ctx   + ((size_t)bh * SDIM + qw) * DDIM;
    __half* Ww  = g_W16 + ((size_t)bh * SDIM + qw) * SDIM;

    // ---- chunk-0 loads ----
#pragma unroll
    for (int j = 0; j < 2; j++) {
        int i = t + THREADS * j, row = i >> 3, seg = i & 7;
        cp16(Ksm + row * KSTRH + seg * 8, KhB + (size_t)row * DDIM + seg * 8);
        cp16(Vsm + row * VSTRH + seg * 8, VtB + (size_t)row * SDIM + seg * 8);
    }
    CP_COMMIT();

    // ---- mask words for chunk 0 (register prefetch) ----
    uint64_t pm0 = Mp0[0], pm1 = Mp1[0];

    // ---- Q A-fragments (fp16, 4 k16-steps) from gmem once ----
    uint32_t aq[4][4];
#pragma unroll
    for (int kb = 0; kb < 4; kb++) {
        float2 q00 = *(const float2*)(Qw + (size_t)grp * DDIM + kb * 16 + 2 * tig);
        float2 q10 = *(const float2*)(Qw + (size_t)(grp + 8) * DDIM + kb * 16 + 2 * tig);
        float2 q01 = *(const float2*)(Qw + (size_t)grp * DDIM + kb * 16 + 2 * tig + 8);
        float2 q11 = *(const float2*)(Qw + (size_t)(grp + 8) * DDIM + kb * 16 + 2 * tig + 8);
        aq[kb][0] = f22h(q00.x, q00.y);
        aq[kb][1] = f22h(q10.x, q10.y);
        aq[kb][2] = f22h(q01.x, q01.y);
        aq[kb][3] = f22h(q11.x, q11.y);
    }

    float sum0 = 0.f, sum1 = 0.f;
    float cc[8][4];
#pragma unroll
    for (int dt = 0; dt < 8; dt++)
#pragma unroll
        for (int r = 0; r < 4; r++) cc[dt][r] = 0.f;

    // ================= chunk loop =================
    for (int c = 0; c < NCH; c++) {
        CP_WAIT0();
        __syncthreads();
        // current-chunk mask bits; prefetch next chunk's words
        const uint32_t ml0 = (uint32_t)pm0, mh0 = (uint32_t)(pm0 >> 32);
        const uint32_t ml1 = (uint32_t)pm1, mh1 = (uint32_t)(pm1 >> 32);
        if (c + 1 < NCH) {
            pm0 = Mp0[c + 1];
            pm1 = Mp1[c + 1];
            __half* kd = Ksm + ((c + 1) & 1) * (64 * KSTRH);
            __half* vd = Vsm + ((c + 1) & 1) * (64 * VSTRH);
            const __half* ks = KhB + (size_t)(c + 1) * CK * DDIM;
            const __half* vs = VtB + (size_t)(c + 1) * CK;
#pragma unroll
            for (int j = 0; j < 2; j++) {
                int i = t + THREADS * j, row = i >> 3, seg = i & 7;
                cp16(kd + row * KSTRH + seg * 8, ks + (size_t)row * DDIM + seg * 8);
                cp16(vd + row * VSTRH + seg * 8, vs + (size_t)row * SDIM + seg * 8);
            }
            CP_COMMIT();
        }
        const __half* Kc = Ksm + (c & 1) * (64 * KSTRH);
        const __half* Vc = Vsm + (c & 1) * (64 * VSTRH);

#pragma unroll
        for (int s = 0; s < 2; s++) {
            const uint32_t mw0 = s ? mh0 : ml0;
            const uint32_t mw1 = s ? mh1 : ml1;

            float sa[4][4];
#pragma unroll
            for (int n2 = 0; n2 < 4; n2++) {
                const int nt = s * 4 + n2;
                float acc[4] = {0.f, 0.f, 0.f, 0.f};
                const __half* kr = Kc + (nt * 8 + grp) * KSTRH + 2 * tig;
#pragma unroll
                for (int kb = 0; kb < 4; kb++) {
                    uint32_t b0 = *(const uint32_t*)(kr + kb * 16);
                    uint32_t b1 = *(const uint32_t*)(kr + kb * 16 + 8);
                    mma_f16(acc, aq[kb][0], aq[kb][1], aq[kb][2], aq[kb][3], b0, b1);
                }
                sa[n2][0] = acc[0]; sa[n2][1] = acc[1];
                sa[n2][2] = acc[2]; sa[n2][3] = acc[3];
            }

            uint32_t eL[4], eH[4];
#pragma unroll
            for (int n2 = 0; n2 < 4; n2++) {
                const int nt = s * 4 + n2;
                const int k0 = n2 * 8 + tig * 2;
                float e00 = (mw0 >> k0) & 1        ? 0.f : __expf(sa[n2][0] * SCALE);
                float e01 = (mw0 >> (k0 + 1)) & 1  ? 0.f : __expf(sa[n2][1] * SCALE);
                float e10 = (mw1 >> k0) & 1        ? 0.f : __expf(sa[n2][2] * SCALE);
                float e11 = (mw1 >> (k0 + 1)) & 1  ? 0.f : __expf(sa[n2][3] * SCALE);
                sum0 += e00 + e01;
                sum1 += e10 + e11;
                eL[n2] = f22h(e00, e01);
                eH[n2] = f22h(e10, e11);
                stg_cs32(Ww + (size_t)grp * SDIM + c * CK + nt * 8 + tig * 2, eL[n2]);
                stg_cs32(Ww + (size_t)(grp + 8) * SDIM + c * CK + nt * 8 + tig * 2, eH[n2]);
            }

#pragma unroll
            for (int g = 0; g < 2; g++) {
                const uint32_t a0 = eL[2 * g], a2 = eL[2 * g + 1];
                const uint32_t a1 = eH[2 * g], a3 = eH[2 * g + 1];
                const int kb0 = s * 32 + g * 16;
#pragma unroll
                for (int dt = 0; dt < 8; dt++) {
                    const __half* vr = Vc + (dt * 8 + grp) * VSTRH + kb0 + 2 * tig;
                    uint32_t b0 = *(const uint32_t*)(vr);
                    uint32_t b1 = *(const uint32_t*)(vr + 8);
                    mma_f16(cc[dt], a0, a1, a2, a3, b0, b1);
                }
            }
        }
    }

    // ================= epilogue (warp-private rows) =================
    sum0 += __shfl_xor_sync(0xffffffffu, sum0, 1);
    sum0 += __shfl_xor_sync(0xffffffffu, sum0, 2);
    sum1 += __shfl_xor_sync(0xffffffffu, sum1, 1);
    sum1 += __shfl_xor_sync(0xffffffffu, sum1, 2);
    const float ri0 = 1.0f / sum0, ri1 = 1.0f / sum1;
    if (tig == 0) {
        g_ri[(size_t)bh * SDIM + qw + grp]     = ri0;
        g_ri[(size_t)bh * SDIM + qw + grp + 8] = ri1;
    }
#pragma unroll
    for (int dt = 0; dt < 8; dt++) {
        *(float2*)(Cw + (size_t)grp * DDIM + dt * 8 + tig * 2) =
            make_float2(cc[dt][0] * ri0, cc[dt][1] * ri0);
        *(float2*)(Cw + (size_t)(grp + 8) * DDIM + dt * 8 + tig * 2) =
            make_float2(cc[dt][2] * ri1, cc[dt][3] * ri1);
    }
}

// ---- pass 2: w_fp32 = fp16_w * rinv ----
__global__ __launch_bounds__(128)
void attn_pass2(float* __restrict__ wout)
{
    const int row = blockIdx.x;
    const float ri = g_ri[row];
    const uint2* s = (const uint2*)(g_W16 + (size_t)row * SDIM);
    float4* p = (float4*)(wout + (size_t)row * SDIM);
#pragma unroll
    for (int j = 0; j < 4; j++) {
        int i4 = threadIdx.x + 128 * j;
        uint2 hv = s[i4];
        float2 f0 = __half22float2(*(const __half2*)&hv.x);
        float2 f1 = __half22float2(*(const __half2*)&hv.y);
        p[i4] = make_float4(f0.x * ri, f0.y * ri, f1.x * ri, f1.y * ri);
    }
}

extern "C" void kernel_launch(void* const* d_in, const int* in_sizes, int n_in,
                              void* d_out, int out_size)
{
    const float* Q = (const float*)d_in[0];
    const float* K = (const float*)d_in[1];
    const float* V = (const float*)d_in[2];
    const int*   M = (const int*)d_in[3];

    float* ctx  = (float*)d_out;
    float* wout = (float*)d_out + (size_t)BHN * SDIM * DDIM;

    prep_k<<<(BHN * SDIM * DDIM) / (256 * 4), 256>>>(K);
    prep_v<<<dim3(SDIM / 64, BHN), 256>>>(V);
    prep_m<<<(BHN * SDIM) / (8 * 4), 256>>>(M);   // 2048 blocks x 8 warps x 4 rows

    cudaFuncSetAttribute(attn_pass1,
                         cudaFuncAttributeMaxDynamicSharedMemorySize, SMEM_BYTES);

    dim3 grid1(SDIM / TQ, BHN);
    attn_pass1<<<grid1, THREADS, SMEM_BYTES>>>(Q, ctx);
    attn_pass2<<<BHN * SDIM, 128>>>(wout);
}

// round 15
// speedup vs baseline: 1.0437x; 1.0437x over previous
#include <cuda_runtime.h>
#include <cuda_fp16.h>
#include <cstdint>

// B=2, H=16, S=2048, D=64 fp32 attention; out = [context | weights].
// prep_k/prep_v: K -> fp16 natural, V -> fp16 transposed [d][s].
// prep_m: mask int32 -> bitpacked uint4 per 128 keys (word k&3, bit k>>2).
// Pass 1: flash-style (no online max), fp16 m16n8k16 mma, ldmatrix.x4 B-frags,
//         bit-mask from registers, fp16 unnormalized weights to scratch (.cs).
// Pass 2: w_fp32 = fp16_w * rinv.

#define SDIM    2048
#define DDIM    64
#define BHN     32
#define TQ      128
#define WQ      16
#define CK      64
#define NCH     32
#define KSTRH   88      // halfs; LDSM phases conflict-free (stride 176B)
#define VSTRH   88
#define THREADS 256
#define SCALE   0.125f

// bytes: K 2*64*88*2 = 22528 | V 22528 -> 45056 B
#define SMEM_BYTES (22528 + 22528)

__device__ float    g_ri[BHN * SDIM];
__device__ __half   g_Kh [(size_t)BHN * SDIM * DDIM];
__device__ __half   g_Vt [(size_t)BHN * DDIM * SDIM];
__device__ __half   g_W16[(size_t)BHN * SDIM * SDIM];        // 268 MB scratch
__device__ uint4    g_Mp [(size_t)BHN * SDIM * (SDIM / 128)]; // 16.8 MB packed mask

__device__ __forceinline__ uint32_t f22h(float x, float y) {
    __half2 h = __floats2half2_rn(x, y);
    return *(uint32_t*)&h;
}

__device__ __forceinline__ void mma_f16(float c[4],
    uint32_t a0, uint32_t a1, uint32_t a2, uint32_t a3,
    uint32_t b0, uint32_t b1)
{
    asm volatile(
        "mma.sync.aligned.m16n8k16.row.col.f32.f16.f16.f32 "
        "{%0,%1,%2,%3}, {%4,%5,%6,%7}, {%8,%9}, {%0,%1,%2,%3};"
        : "+f"(c[0]), "+f"(c[1]), "+f"(c[2]), "+f"(c[3])
        : "r"(a0), "r"(a1), "r"(a2), "r"(a3), "r"(b0), "r"(b1));
}

#define LDSM_X4(r, addr) \
    asm volatile("ldmatrix.sync.aligned.m8n8.x4.shared.b16 {%0,%1,%2,%3}, [%4];" \
        : "=r"((r)[0]), "=r"((r)[1]), "=r"((r)[2]), "=r"((r)[3]) : "r"(addr))

__device__ __forceinline__ void cp16(void* dst_smem, const void* src) {
    uint32_t d = (uint32_t)__cvta_generic_to_shared(dst_smem);
    asm volatile("cp.async.cg.shared.global [%0], [%1], 16;" :: "r"(d), "l"(src));
}
__device__ __forceinline__ void stg_cs32(__half* p, uint32_t v) {
    asm volatile("st.global.cs.u32 [%0], %1;" :: "l"(p), "r"(v) : "memory");
}
#define CP_COMMIT()  asm volatile("cp.async.commit_group;" ::: "memory")
#define CP_WAIT0()   asm volatile("cp.async.wait_group 0;" ::: "memory")

// ---- prep: K fp32 -> fp16 natural ----
__global__ __launch_bounds__(256)
void prep_k(const float* __restrict__ K)
{
    size_t i = ((size_t)blockIdx.x * 256 + threadIdx.x) * 4;
    float4 v = *(const float4*)(K + i);
    __half2* o = (__half2*)(g_Kh + i);
    o[0] = __floats2half2_rn(v.x, v.y);
    o[1] = __floats2half2_rn(v.z, v.w);
}

// ---- prep: V fp32 [s][d] -> fp16 transposed [d][s] ----
__global__ __launch_bounds__(256)
void prep_v(const float* __restrict__ V)
{
    __shared__ float tile[64][65];
    const int bh = blockIdx.y, s0 = blockIdx.x * 64;
    const float* Vb = V + ((size_t)bh * SDIM + s0) * DDIM;
    const int t = threadIdx.x;
#pragma unroll
    for (int j = 0; j < 4; j++) {
        int i = t + 256 * j, r = i >> 4, c4 = i & 15;
        float4 v = *(const float4*)(Vb + (size_t)r * DDIM + c4 * 4);
        tile[r][c4 * 4 + 0] = v.x; tile[r][c4 * 4 + 1] = v.y;
        tile[r][c4 * 4 + 2] = v.z; tile[r][c4 * 4 + 3] = v.w;
    }
    __syncthreads();
    const int d = t >> 2, sb = (t & 3) * 16;
    __half2* o = (__half2*)(g_Vt + ((size_t)bh * DDIM + d) * SDIM + s0 + sb);
#pragma unroll
    for (int k = 0; k < 8; k++)
        o[k] = __floats2half2_rn(tile[sb + 2 * k][d], tile[sb + 2 * k + 1][d]);
}

// ---- prep: mask -> packed uint4 per 128 keys. key k: word k&3, bit k>>2 ----
__global__ __launch_bounds__(256)
void prep_m(const int* __restrict__ M)
{
    const int row  = (int)blockIdx.x * 8 + (int)(threadIdx.x >> 5);
    const int lane = threadIdx.x & 31;
    const int4* mr = (const int4*)(M + (size_t)row * SDIM);
    uint4* out = g_Mp + (size_t)row * 16;
#pragma unroll 4
    for (int it = 0; it < 16; it++) {
        int4 v = mr[it * 32 + lane];             // keys 128*it + 4*lane + {0..3}
        uint32_t nib = (v.x != 0) | ((v.y != 0) << 1)
                     | ((v.z != 0) << 2) | ((v.w != 0) << 3);
        uint32_t b0 = __ballot_sync(0xffffffffu, nib & 1);
        uint32_t b1 = __ballot_sync(0xffffffffu, nib & 2);
        uint32_t b2 = __ballot_sync(0xffffffffu, nib & 4);
        uint32_t b3 = __ballot_sync(0xffffffffu, nib & 8);
        if (lane == 0) out[it] = make_uint4(b0, b1, b2, b3);
    }
}

__global__ __launch_bounds__(THREADS, 2)
void attn_pass1(const float* __restrict__ Q, float* __restrict__ ctx)
{
    extern __shared__ __half smh[];
    __half* Ksm = smh;                        // [2][64 x 88]
    __half* Vsm = smh + 2 * 64 * KSTRH;       // [2][64 x 88]

    const int t    = threadIdx.x;
    const int w    = t >> 5;
    const int lane = t & 31;
    const int grp  = lane >> 2;
    const int tig  = lane & 3;
    const int bh   = blockIdx.y;
    const int qw   = blockIdx.x * TQ + w * WQ;

    const __half* KhB = g_Kh + (size_t)bh * SDIM * DDIM;
    const __half* VtB = g_Vt + (size_t)bh * DDIM * SDIM;
    const float* Qw = Q + ((size_t)bh * SDIM + qw) * DDIM;
    const uint4* Mp0 = g_Mp + ((size_t)bh * SDIM + qw + grp) * 16;
    const uint4* Mp1 = Mp0 + 8 * 16;
    float*  Cw  = ctx   + ((size_t)bh * SDIM + qw) * DDIM;
    __half* Ww  = g_W16 + ((size_t)bh * SDIM + qw) * SDIM;

    // ---- chunk-0 loads ----
#pragma unroll
    for (int j = 0; j < 2; j++) {
        int i = t + THREADS * j, row = i >> 3, seg = i & 7;
        cp16(Ksm + row * KSTRH + seg * 8, KhB + (size_t)row * DDIM + seg * 8);
        cp16(Vsm + row * VSTRH + seg * 8, VtB + (size_t)row * SDIM + seg * 8);
    }
    CP_COMMIT();

    // ---- mask group 0 (keys 0..127) ----
    uint4 cm0 = Mp0[0], cm1 = Mp1[0];
    uint4 nx0, nx1;

    // ---- Q A-fragments ----
    uint32_t aq[4][4];
#pragma unroll
    for (int kb = 0; kb < 4; kb++) {
        float2 q00 = *(const float2*)(Qw + (size_t)grp * DDIM + kb * 16 + 2 * tig);
        float2 q10 = *(const float2*)(Qw + (size_t)(grp + 8) * DDIM + kb * 16 + 2 * tig);
        float2 q01 = *(const float2*)(Qw + (size_t)grp * DDIM + kb * 16 + 2 * tig + 8);
        float2 q11 = *(const float2*)(Qw + (size_t)(grp + 8) * DDIM + kb * 16 + 2 * tig + 8);
        aq[kb][0] = f22h(q00.x, q00.y);
        aq[kb][1] = f22h(q10.x, q10.y);
        aq[kb][2] = f22h(q01.x, q01.y);
        aq[kb][3] = f22h(q11.x, q11.y);
    }

    // ---- per-lane LDSM base offsets (bytes) ----
    const uint32_t kfo = ((lane & 7) * KSTRH + (lane >> 4) * 16 + ((lane >> 3) & 1) * 8) * 2;
    const uint32_t vfo = (((lane >> 4) * 8 + (lane & 7)) * VSTRH + ((lane >> 3) & 1) * 8) * 2;
    const uint32_t ksm0 = (uint32_t)__cvta_generic_to_shared(Ksm);
    const uint32_t vsm0 = (uint32_t)__cvta_generic_to_shared(Vsm);

    float sum0 = 0.f, sum1 = 0.f;
    float cc[8][4];
#pragma unroll
    for (int dt = 0; dt < 8; dt++)
#pragma unroll
        for (int r = 0; r < 4; r++) cc[dt][r] = 0.f;

    // thread-constant mask word selectors / bit base
    const bool hiw  = tig & 1;
    const int  bitb = tig >> 1;

    // ================= chunk loop =================
    for (int c = 0; c < NCH; c++) {
        CP_WAIT0();
        __syncthreads();
        const int par = c & 1;
        if (par == 0 && c + 2 < NCH) {           // prefetch next 128-key group
            nx0 = Mp0[(c >> 1) + 1];
            nx1 = Mp1[(c >> 1) + 1];
        }
        if (c + 1 < NCH) {
            __half* kd = Ksm + ((c + 1) & 1) * (64 * KSTRH);
            __half* vd = Vsm + ((c + 1) & 1) * (64 * VSTRH);
            const __half* ks = KhB + (size_t)(c + 1) * CK * DDIM;
            const __half* vs = VtB + (size_t)(c + 1) * CK;
#pragma unroll
            for (int j = 0; j < 2; j++) {
                int i = t + THREADS * j, row = i >> 3, seg = i & 7;
                cp16(kd + row * KSTRH + seg * 8, ks + (size_t)row * DDIM + seg * 8);
                cp16(vd + row * VSTRH + seg * 8, vs + (size_t)row * SDIM + seg * 8);
            }
            CP_COMMIT();
        }
        const uint32_t kbase = ksm0 + (c & 1) * (64 * KSTRH * 2) + kfo;
        const uint32_t vbase = vsm0 + (c & 1) * (64 * VSTRH * 2) + vfo;

        const uint32_t mwA0 = hiw ? cm0.z : cm0.x;
        const uint32_t mwB0 = hiw ? cm0.w : cm0.y;
        const uint32_t mwA1 = hiw ? cm1.z : cm1.x;
        const uint32_t mwB1 = hiw ? cm1.w : cm1.y;

#pragma unroll
        for (int s = 0; s < 2; s++) {
            // ---- scores: 4 n-tiles via ldmatrix.x4 ----
            float sa[4][4];
#pragma unroll
            for (int n2 = 0; n2 < 4; n2++) {
                const int nt = s * 4 + n2;
                const uint32_t ka = kbase + nt * (8 * KSTRH * 2);
                uint32_t b01[4], b23[4];
                LDSM_X4(b01, ka);
                LDSM_X4(b23, ka + 64);
                float acc[4] = {0.f, 0.f, 0.f, 0.f};
                mma_f16(acc, aq[0][0], aq[0][1], aq[0][2], aq[0][3], b01[0], b01[1]);
                mma_f16(acc, aq[1][0], aq[1][1], aq[1][2], aq[1][3], b01[2], b01[3]);
                mma_f16(acc, aq[2][0], aq[2][1], aq[2][2], aq[2][3], b23[0], b23[1]);
                mma_f16(acc, aq[3][0], aq[3][1], aq[3][2], aq[3][3], b23[2], b23[3]);
                sa[n2][0] = acc[0]; sa[n2][1] = acc[1];
                sa[n2][2] = acc[2]; sa[n2][3] = acc[3];
            }

            // ---- exp with register mask bits; W16 stores ----
            uint32_t eL[4], eH[4];
#pragma unroll
            for (int n2 = 0; n2 < 4; n2++) {
                const int nt  = s * 4 + n2;
                const int bit = par * 16 + s * 8 + n2 * 2 + bitb;
                float e00 = (mwA0 >> bit) & 1 ? 0.f : __expf(sa[n2][0] * SCALE);
                float e01 = (mwB0 >> bit) & 1 ? 0.f : __expf(sa[n2][1] * SCALE);
                float e10 = (mwA1 >> bit) & 1 ? 0.f : __expf(sa[n2][2] * SCALE);
                float e11 = (mwB1 >> bit) & 1 ? 0.f : __expf(sa[n2][3] * SCALE);
                sum0 += e00 + e01;
                sum1 += e10 + e11;
                eL[n2] = f22h(e00, e01);
                eH[n2] = f22h(e10, e11);
                stg_cs32(Ww + (size_t)grp * SDIM + c * CK + nt * 8 + tig * 2, eL[n2]);
                stg_cs32(Ww + (size_t)(grp + 8) * SDIM + c * CK + nt * 8 + tig * 2, eH[n2]);
            }

            // ---- context: ldmatrix.x4 V frags, 2 k16-groups ----
#pragma unroll
            for (int g = 0; g < 2; g++) {
                const uint32_t a0 = eL[2 * g], a2 = eL[2 * g + 1];
                const uint32_t a1 = eH[2 * g], a3 = eH[2 * g + 1];
                const uint32_t off = (s * 32 + g * 16) * 2;
#pragma unroll
                for (int dtp = 0; dtp < 4; dtp++) {
                    uint32_t vb[4];
                    LDSM_X4(vb, vbase + dtp * (16 * VSTRH * 2) + off);
                    mma_f16(cc[2 * dtp],     a0, a1, a2, a3, vb[0], vb[1]);
                    mma_f16(cc[2 * dtp + 1], a0, a1, a2, a3, vb[2], vb[3]);
                }
            }
        }
        if (par == 1) { cm0 = nx0; cm1 = nx1; }
    }

    // ================= epilogue (warp-private rows) =================
    sum0 += __shfl_xor_sync(0xffffffffu, sum0, 1);
    sum0 += __shfl_xor_sync(0xffffffffu, sum0, 2);
    sum1 += __shfl_xor_sync(0xffffffffu, sum1, 1);
    sum1 += __shfl_xor_sync(0xffffffffu, sum1, 2);
    const float ri0 = 1.0f / sum0, ri1 = 1.0f / sum1;
    if (tig == 0) {
        g_ri[(size_t)bh * SDIM + qw + grp]     = ri0;
        g_ri[(size_t)bh * SDIM + qw + grp + 8] = ri1;
    }
#pragma unroll
    for (int dt = 0; dt < 8; dt++) {
        *(float2*)(Cw + (size_t)grp * DDIM + dt * 8 + tig * 2) =
            make_float2(cc[dt][0] * ri0, cc[dt][1] * ri0);
        *(float2*)(Cw + (size_t)(grp + 8) * DDIM + dt * 8 + tig * 2) =
            make_float2(cc[dt][2] * ri1, cc[dt][3] * ri1);
    }
}

// ---- pass 2: w_fp32 = fp16_w * rinv ----
__global__ __launch_bounds__(128)
void attn_pass2(float* __restrict__ wout)
{
    const int row = blockIdx.x;
    const float ri = g_ri[row];
    const uint2* s = (const uint2*)(g_W16 + (size_t)row * SDIM);
    float4* p = (float4*)(wout + (size_t)row * SDIM);
#pragma unroll
    for (int j = 0; j < 4; j++) {
        int i4 = threadIdx.x + 128 * j;
        uint2 hv = s[i4];
        float2 f0 = __half22float2(*(const __half2*)&hv.x);
        float2 f1 = __half22float2(*(const __half2*)&hv.y);
        p[i4] = make_float4(f0.x * ri, f0.y * ri, f1.x * ri, f1.y * ri);
    }
}

extern "C" void kernel_launch(void* const* d_in, const int* in_sizes, int n_in,
                              void* d_out, int out_size)
{
    const float* Q = (const float*)d_in[0];
    const float* K = (const float*)d_in[1];
    const float* V = (const float*)d_in[2];
    const int*   M = (const int*)d_in[3];

    float* ctx  = (float*)d_out;
    float* wout = (float*)d_out + (size_t)BHN * SDIM * DDIM;

    prep_k<<<(BHN * SDIM * DDIM) / (256 * 4), 256>>>(K);
    prep_v<<<dim3(SDIM / 64, BHN), 256>>>(V);
    prep_m<<<(BHN * SDIM) / 8, 256>>>(M);     // 1 warp per row

    cudaFuncSetAttribute(attn_pass1,
                         cudaFuncAttributeMaxDynamicSharedMemorySize, SMEM_BYTES);

    dim3 grid1(SDIM / TQ, BHN);
    attn_pass1<<<grid1, THREADS, SMEM_BYTES>>>(Q, ctx);
    attn_pass2<<<BHN * SDIM, 128>>>(wout);
}

// round 16
// speedup vs baseline: 1.0791x; 1.0339x over previous
#include <cuda_runtime.h>
#include <cuda_fp16.h>
#include <cstdint>

// B=2, H=16, S=2048, D=64 fp32 attention; out = [context | weights].
// prep_k/prep_v: K -> fp16 natural, V -> fp16 transposed [d][s].
// prep_m: mask int32 -> bitpacked uint4 per 128 keys (word k&3, bit k>>2).
// Pass 1: sums + context only (no weight stores): fp16 mma, ldmatrix frags.
// Pass 2: RECOMPUTES scores (K fp16 from L2), w = exp(s)*ri -> fp32 out.

#define SDIM    2048
#define DDIM    64
#define BHN     32
#define TQ      128
#define WQ      16
#define CK      64
#define NCH     32
#define KSTRH   88
#define VSTRH   88
#define THREADS 256
#define SCALE   0.125f

#define SMEM_BYTES1 (22528 + 22528)   // pass1: K + V double buffers
#define SMEM_BYTES2 (22528)           // pass2: K double buffer only

__device__ float    g_ri[BHN * SDIM];
__device__ __half   g_Kh [(size_t)BHN * SDIM * DDIM];
__device__ __half   g_Vt [(size_t)BHN * DDIM * SDIM];
__device__ uint4    g_Mp [(size_t)BHN * SDIM * (SDIM / 128)]; // 16.8 MB packed mask

__device__ __forceinline__ uint32_t f22h(float x, float y) {
    __half2 h = __floats2half2_rn(x, y);
    return *(uint32_t*)&h;
}

__device__ __forceinline__ void mma_f16(float c[4],
    uint32_t a0, uint32_t a1, uint32_t a2, uint32_t a3,
    uint32_t b0, uint32_t b1)
{
    asm volatile(
        "mma.sync.aligned.m16n8k16.row.col.f32.f16.f16.f32 "
        "{%0,%1,%2,%3}, {%4,%5,%6,%7}, {%8,%9}, {%0,%1,%2,%3};"
        : "+f"(c[0]), "+f"(c[1]), "+f"(c[2]), "+f"(c[3])
        : "r"(a0), "r"(a1), "r"(a2), "r"(a3), "r"(b0), "r"(b1));
}

#define LDSM_X4(r, addr) \
    asm volatile("ldmatrix.sync.aligned.m8n8.x4.shared.b16 {%0,%1,%2,%3}, [%4];" \
        : "=r"((r)[0]), "=r"((r)[1]), "=r"((r)[2]), "=r"((r)[3]) : "r"(addr))

__device__ __forceinline__ void cp16(void* dst_smem, const void* src) {
    uint32_t d = (uint32_t)__cvta_generic_to_shared(dst_smem);
    asm volatile("cp.async.cg.shared.global [%0], [%1], 16;" :: "r"(d), "l"(src));
}
__device__ __forceinline__ void stg_cs64(float* p, float2 v) {
    asm volatile("st.global.cs.v2.f32 [%0], {%1,%2};" :: "l"(p), "f"(v.x), "f"(v.y) : "memory");
}
#define CP_COMMIT()  asm volatile("cp.async.commit_group;" ::: "memory")
#define CP_WAIT0()   asm volatile("cp.async.wait_group 0;" ::: "memory")

// ---- prep: K fp32 -> fp16 natural ----
__global__ __launch_bounds__(256)
void prep_k(const float* __restrict__ K)
{
    size_t i = ((size_t)blockIdx.x * 256 + threadIdx.x) * 4;
    float4 v = *(const float4*)(K + i);
    __half2* o = (__half2*)(g_Kh + i);
    o[0] = __floats2half2_rn(v.x, v.y);
    o[1] = __floats2half2_rn(v.z, v.w);
}

// ---- prep: V fp32 [s][d] -> fp16 transposed [d][s] ----
__global__ __launch_bounds__(256)
void prep_v(const float* __restrict__ V)
{
    __shared__ float tile[64][65];
    const int bh = blockIdx.y, s0 = blockIdx.x * 64;
    const float* Vb = V + ((size_t)bh * SDIM + s0) * DDIM;
    const int t = threadIdx.x;
#pragma unroll
    for (int j = 0; j < 4; j++) {
        int i = t + 256 * j, r = i >> 4, c4 = i & 15;
        float4 v = *(const float4*)(Vb + (size_t)r * DDIM + c4 * 4);
        tile[r][c4 * 4 + 0] = v.x; tile[r][c4 * 4 + 1] = v.y;
        tile[r][c4 * 4 + 2] = v.z; tile[r][c4 * 4 + 3] = v.w;
    }
    __syncthreads();
    const int d = t >> 2, sb = (t & 3) * 16;
    __half2* o = (__half2*)(g_Vt + ((size_t)bh * DDIM + d) * SDIM + s0 + sb);
#pragma unroll
    for (int k = 0; k < 8; k++)
        o[k] = __floats2half2_rn(tile[sb + 2 * k][d], tile[sb + 2 * k + 1][d]);
}

// ---- prep: mask -> packed uint4 per 128 keys. key k: word k&3, bit k>>2 ----
__global__ __launch_bounds__(256)
void prep_m(const int* __restrict__ M)
{
    const int row  = (int)blockIdx.x * 8 + (int)(threadIdx.x >> 5);
    const int lane = threadIdx.x & 31;
    const int4* mr = (const int4*)(M + (size_t)row * SDIM);
    uint4* out = g_Mp + (size_t)row * 16;
#pragma unroll 4
    for (int it = 0; it < 16; it++) {
        int4 v = mr[it * 32 + lane];
        uint32_t nib = (v.x != 0) | ((v.y != 0) << 1)
                     | ((v.z != 0) << 2) | ((v.w != 0) << 3);
        uint32_t b0 = __ballot_sync(0xffffffffu, nib & 1);
        uint32_t b1 = __ballot_sync(0xffffffffu, nib & 2);
        uint32_t b2 = __ballot_sync(0xffffffffu, nib & 4);
        uint32_t b3 = __ballot_sync(0xffffffffu, nib & 8);
        if (lane == 0) out[it] = make_uint4(b0, b1, b2, b3);
    }
}

// =================== pass 1: row sums + context only ===================
__global__ __launch_bounds__(THREADS, 2)
void attn_pass1(const float* __restrict__ Q, float* __restrict__ ctx)
{
    extern __shared__ __half smh[];
    __half* Ksm = smh;                        // [2][64 x 88]
    __half* Vsm = smh + 2 * 64 * KSTRH;       // [2][64 x 88]

    const int t    = threadIdx.x;
    const int w    = t >> 5;
    const int lane = t & 31;
    const int grp  = lane >> 2;
    const int tig  = lane & 3;
    const int bh   = blockIdx.y;
    const int qw   = blockIdx.x * TQ + w * WQ;

    const __half* KhB = g_Kh + (size_t)bh * SDIM * DDIM;
    const __half* VtB = g_Vt + (size_t)bh * DDIM * SDIM;
    const float* Qw = Q + ((size_t)bh * SDIM + qw) * DDIM;
    const uint4* Mp0 = g_Mp + ((size_t)bh * SDIM + qw + grp) * 16;
    const uint4* Mp1 = Mp0 + 8 * 16;
    float* Cw = ctx + ((size_t)bh * SDIM + qw) * DDIM;

#pragma unroll
    for (int j = 0; j < 2; j++) {
        int i = t + THREADS * j, row = i >> 3, seg = i & 7;
        cp16(Ksm + row * KSTRH + seg * 8, KhB + (size_t)row * DDIM + seg * 8);
        cp16(Vsm + row * VSTRH + seg * 8, VtB + (size_t)row * SDIM + seg * 8);
    }
    CP_COMMIT();

    uint4 cm0 = Mp0[0], cm1 = Mp1[0];
    uint4 nx0, nx1;

    uint32_t aq[4][4];
#pragma unroll
    for (int kb = 0; kb < 4; kb++) {
        float2 q00 = *(const float2*)(Qw + (size_t)grp * DDIM + kb * 16 + 2 * tig);
        float2 q10 = *(const float2*)(Qw + (size_t)(grp + 8) * DDIM + kb * 16 + 2 * tig);
        float2 q01 = *(const float2*)(Qw + (size_t)grp * DDIM + kb * 16 + 2 * tig + 8);
        float2 q11 = *(const float2*)(Qw + (size_t)(grp + 8) * DDIM + kb * 16 + 2 * tig + 8);
        aq[kb][0] = f22h(q00.x, q00.y);
        aq[kb][1] = f22h(q10.x, q10.y);
        aq[kb][2] = f22h(q01.x, q01.y);
        aq[kb][3] = f22h(q11.x, q11.y);
    }

    const uint32_t kfo = ((lane & 7) * KSTRH + (lane >> 4) * 16 + ((lane >> 3) & 1) * 8) * 2;
    const uint32_t vfo = (((lane >> 4) * 8 + (lane & 7)) * VSTRH + ((lane >> 3) & 1) * 8) * 2;
    const uint32_t ksm0 = (uint32_t)__cvta_generic_to_shared(Ksm);
    const uint32_t vsm0 = (uint32_t)__cvta_generic_to_shared(Vsm);

    float sum0 = 0.f, sum1 = 0.f;
    float cc[8][4];
#pragma unroll
    for (int dt = 0; dt < 8; dt++)
#pragma unroll
        for (int r = 0; r < 4; r++) cc[dt][r] = 0.f;

    const bool hiw  = tig & 1;
    const int  bitb = tig >> 1;

    for (int c = 0; c < NCH; c++) {
        CP_WAIT0();
        __syncthreads();
        const int par = c & 1;
        if (par == 0 && c + 2 < NCH) {
            nx0 = Mp0[(c >> 1) + 1];
            nx1 = Mp1[(c >> 1) + 1];
        }
        if (c + 1 < NCH) {
            __half* kd = Ksm + ((c + 1) & 1) * (64 * KSTRH);
            __half* vd = Vsm + ((c + 1) & 1) * (64 * VSTRH);
            const __half* ks = KhB + (size_t)(c + 1) * CK * DDIM;
            const __half* vs = VtB + (size_t)(c + 1) * CK;
#pragma unroll
            for (int j = 0; j < 2; j++) {
                int i = t + THREADS * j, row = i >> 3, seg = i & 7;
                cp16(kd + row * KSTRH + seg * 8, ks + (size_t)row * DDIM + seg * 8);
                cp16(vd + row * VSTRH + seg * 8, vs + (size_t)row * SDIM + seg * 8);
            }
            CP_COMMIT();
        }
        const uint32_t kbase = ksm0 + (c & 1) * (64 * KSTRH * 2) + kfo;
        const uint32_t vbase = vsm0 + (c & 1) * (64 * VSTRH * 2) + vfo;

        const uint32_t mwA0 = hiw ? cm0.z : cm0.x;
        const uint32_t mwB0 = hiw ? cm0.w : cm0.y;
        const uint32_t mwA1 = hiw ? cm1.z : cm1.x;
        const uint32_t mwB1 = hiw ? cm1.w : cm1.y;

#pragma unroll
        for (int s = 0; s < 2; s++) {
            float sa[4][4];
#pragma unroll
            for (int n2 = 0; n2 < 4; n2++) {
                const int nt = s * 4 + n2;
                const uint32_t ka = kbase + nt * (8 * KSTRH * 2);
                uint32_t b01[4], b23[4];
                LDSM_X4(b01, ka);
                LDSM_X4(b23, ka + 64);
                float acc[4] = {0.f, 0.f, 0.f, 0.f};
                mma_f16(acc, aq[0][0], aq[0][1], aq[0][2], aq[0][3], b01[0], b01[1]);
                mma_f16(acc, aq[1][0], aq[1][1], aq[1][2], aq[1][3], b01[2], b01[3]);
                mma_f16(acc, aq[2][0], aq[2][1], aq[2][2], aq[2][3], b23[0], b23[1]);
                mma_f16(acc, aq[3][0], aq[3][1], aq[3][2], aq[3][3], b23[2], b23[3]);
                sa[n2][0] = acc[0]; sa[n2][1] = acc[1];
                sa[n2][2] = acc[2]; sa[n2][3] = acc[3];
            }

            uint32_t eL[4], eH[4];
#pragma unroll
            for (int n2 = 0; n2 < 4; n2++) {
                const int bit = par * 16 + s * 8 + n2 * 2 + bitb;
                float e00 = (mwA0 >> bit) & 1 ? 0.f : __expf(sa[n2][0] * SCALE);
                float e01 = (mwB0 >> bit) & 1 ? 0.f : __expf(sa[n2][1] * SCALE);
                float e10 = (mwA1 >> bit) & 1 ? 0.f : __expf(sa[n2][2] * SCALE);
                float e11 = (mwB1 >> bit) & 1 ? 0.f : __expf(sa[n2][3] * SCALE);
                sum0 += e00 + e01;
                sum1 += e10 + e11;
                eL[n2] = f22h(e00, e01);
                eH[n2] = f22h(e10, e11);
            }

#pragma unroll
            for (int g = 0; g < 2; g++) {
                const uint32_t a0 = eL[2 * g], a2 = eL[2 * g + 1];
                const uint32_t a1 = eH[2 * g], a3 = eH[2 * g + 1];
                const uint32_t off = (s * 32 + g * 16) * 2;
#pragma unroll
                for (int dtp = 0; dtp < 4; dtp++) {
                    uint32_t vb[4];
                    LDSM_X4(vb, vbase + dtp * (16 * VSTRH * 2) + off);
                    mma_f16(cc[2 * dtp],     a0, a1, a2, a3, vb[0], vb[1]);
                    mma_f16(cc[2 * dtp + 1], a0, a1, a2, a3, vb[2], vb[3]);
                }
            }
        }
        if (par == 1) { cm0 = nx0; cm1 = nx1; }
    }

    sum0 += __shfl_xor_sync(0xffffffffu, sum0, 1);
    sum0 += __shfl_xor_sync(0xffffffffu, sum0, 2);
    sum1 += __shfl_xor_sync(0xffffffffu, sum1, 1);
    sum1 += __shfl_xor_sync(0xffffffffu, sum1, 2);
    const float ri0 = 1.0f / sum0, ri1 = 1.0f / sum1;
    if (tig == 0) {
        g_ri[(size_t)bh * SDIM + qw + grp]     = ri0;
        g_ri[(size_t)bh * SDIM + qw + grp + 8] = ri1;
    }
#pragma unroll
    for (int dt = 0; dt < 8; dt++) {
        *(float2*)(Cw + (size_t)grp * DDIM + dt * 8 + tig * 2) =
            make_float2(cc[dt][0] * ri0, cc[dt][1] * ri0);
        *(float2*)(Cw + (size_t)(grp + 8) * DDIM + dt * 8 + tig * 2) =
            make_float2(cc[dt][2] * ri1, cc[dt][3] * ri1);
    }
}

// ========= pass 2: recompute scores, w = exp(s)*ri -> fp32 weights =========
__global__ __launch_bounds__(THREADS, 3)
void attn_pass2(const float* __restrict__ Q, float* __restrict__ wout)
{
    extern __shared__ __half smh[];
    __half* Ksm = smh;                        // [2][64 x 88]

    const int t    = threadIdx.x;
    const int lane = t & 31;
    const int w    = t >> 5;
    const int grp  = lane >> 2;
    const int tig  = lane & 3;
    const int bh   = blockIdx.y;
    const int qw   = blockIdx.x * TQ + w * WQ;

    const __half* KhB = g_Kh + (size_t)bh * SDIM * DDIM;
    const float* Qw = Q + ((size_t)bh * SDIM + qw) * DDIM;
    const uint4* Mp0 = g_Mp + ((size_t)bh * SDIM + qw + grp) * 16;
    const uint4* Mp1 = Mp0 + 8 * 16;
    float* Wo = wout + ((size_t)bh * SDIM + qw) * SDIM;

    const float ri0 = g_ri[(size_t)bh * SDIM + qw + grp];
    const float ri1 = g_ri[(size_t)bh * SDIM + qw + grp + 8];

#pragma unroll
    for (int j = 0; j < 2; j++) {
        int i = t + THREADS * j, row = i >> 3, seg = i & 7;
        cp16(Ksm + row * KSTRH + seg * 8, KhB + (size_t)row * DDIM + seg * 8);
    }
    CP_COMMIT();

    uint4 cm0 = Mp0[0], cm1 = Mp1[0];
    uint4 nx0, nx1;

    uint32_t aq[4][4];
#pragma unroll
    for (int kb = 0; kb < 4; kb++) {
        float2 q00 = *(const float2*)(Qw + (size_t)grp * DDIM + kb * 16 + 2 * tig);
        float2 q10 = *(const float2*)(Qw + (size_t)(grp + 8) * DDIM + kb * 16 + 2 * tig);
        float2 q01 = *(const float2*)(Qw + (size_t)grp * DDIM + kb * 16 + 2 * tig + 8);
        float2 q11 = *(const float2*)(Qw + (size_t)(grp + 8) * DDIM + kb * 16 + 2 * tig + 8);
        aq[kb][0] = f22h(q00.x, q00.y);
        aq[kb][1] = f22h(q10.x, q10.y);
        aq[kb][2] = f22h(q01.x, q01.y);
        aq[kb][3] = f22h(q11.x, q11.y);
    }

    const uint32_t kfo = ((lane & 7) * KSTRH + (lane >> 4) * 16 + ((lane >> 3) & 1) * 8) * 2;
    const uint32_t ksm0 = (uint32_t)__cvta_generic_to_shared(Ksm);
    const bool hiw  = tig & 1;
    const int  bitb = tig >> 1;

    for (int c = 0; c < NCH; c++) {
        CP_WAIT0();
        __syncthreads();
        const int par = c & 1;
        if (par == 0 && c + 2 < NCH) {
            nx0 = Mp0[(c >> 1) + 1];
            nx1 = Mp1[(c >> 1) + 1];
        }
        if (c + 1 < NCH) {
            __half* kd = Ksm + ((c + 1) & 1) * (64 * KSTRH);
            const __half* ks = KhB + (size_t)(c + 1) * CK * DDIM;
#pragma unroll
            for (int j = 0; j < 2; j++) {
                int i = t + THREADS * j, row = i >> 3, seg = i & 7;
                cp16(kd + row * KSTRH + seg * 8, ks + (size_t)row * DDIM + seg * 8);
            }
            CP_COMMIT();
        }
        const uint32_t kbase = ksm0 + (c & 1) * (64 * KSTRH * 2) + kfo;

        const uint32_t mwA0 = hiw ? cm0.z : cm0.x;
        const uint32_t mwB0 = hiw ? cm0.w : cm0.y;
        const uint32_t mwA1 = hiw ? cm1.z : cm1.x;
        const uint32_t mwB1 = hiw ? cm1.w : cm1.y;

#pragma unroll
        for (int s = 0; s < 2; s++) {
            float sa[4][4];
#pragma unroll
            for (int n2 = 0; n2 < 4; n2++) {
                const int nt = s * 4 + n2;
                const uint32_t ka = kbase + nt * (8 * KSTRH * 2);
                uint32_t b01[4], b23[4];
                LDSM_X4(b01, ka);
                LDSM_X4(b23, ka + 64);
                float acc[4] = {0.f, 0.f, 0.f, 0.f};
                mma_f16(acc, aq[0][0], aq[0][1], aq[0][2], aq[0][3], b01[0], b01[1]);
                mma_f16(acc, aq[1][0], aq[1][1], aq[1][2], aq[1][3], b01[2], b01[3]);
                mma_f16(acc, aq[2][0], aq[2][1], aq[2][2], aq[2][3], b23[0], b23[1]);
                mma_f16(acc, aq[3][0], aq[3][1], aq[3][2], aq[3][3], b23[2], b23[3]);
                sa[n2][0] = acc[0]; sa[n2][1] = acc[1];
                sa[n2][2] = acc[2]; sa[n2][3] = acc[3];
            }

#pragma unroll
            for (int n2 = 0; n2 < 4; n2++) {
                const int nt  = s * 4 + n2;
                const int bit = par * 16 + s * 8 + n2 * 2 + bitb;
                float w00 = (mwA0 >> bit) & 1 ? 0.f : __expf(sa[n2][0] * SCALE) * ri0;
                float w01 = (mwB0 >> bit) & 1 ? 0.f : __expf(sa[n2][1] * SCALE) * ri0;
                float w10 = (mwA1 >> bit) & 1 ? 0.f : __expf(sa[n2][2] * SCALE) * ri1;
                float w11 = (mwB1 >> bit) & 1 ? 0.f : __expf(sa[n2][3] * SCALE) * ri1;
                stg_cs64(Wo + (size_t)grp * SDIM + c * CK + nt * 8 + tig * 2,
                         make_float2(w00, w01));
                stg_cs64(Wo + (size_t)(grp + 8) * SDIM + c * CK + nt * 8 + tig * 2,
                         make_float2(w10, w11));
            }
        }
        if (par == 1) { cm0 = nx0; cm1 = nx1; }
    }
}

extern "C" void kernel_launch(void* const* d_in, const int* in_sizes, int n_in,
                              void* d_out, int out_size)
{
    const float* Q = (const float*)d_in[0];
    const float* K = (const float*)d_in[1];
    const float* V = (const float*)d_in[2];
    const int*   M = (const int*)d_in[3];

    float* ctx  = (float*)d_out;
    float* wout = (float*)d_out + (size_t)BHN * SDIM * DDIM;

    prep_k<<<(BHN * SDIM * DDIM) / (256 * 4), 256>>>(K);
    prep_v<<<dim3(SDIM / 64, BHN), 256>>>(V);
    prep_m<<<(BHN * SDIM) / 8, 256>>>(M);

    cudaFuncSetAttribute(attn_pass1,
                         cudaFuncAttributeMaxDynamicSharedMemorySize, SMEM_BYTES1);
    cudaFuncSetAttribute(attn_pass2,
                         cudaFuncAttributeMaxDynamicSharedMemorySize, SMEM_BYTES2);

    dim3 grid(SDIM / TQ, BHN);
    attn_pass1<<<grid, THREADS, SMEM_BYTES1>>>(Q, ctx);
    attn_pass2<<<grid, THREADS, SMEM_BYTES2>>>(Q, wout);
}

// round 17
// speedup vs baseline: 1.2491x; 1.1575x over previous
#include <cuda_runtime.h>
#include <cuda_fp16.h>
#include <cstdint>

// B=2, H=16, S=2048, D=64 fp32 attention; out = [context | weights].
// prep_k/prep_v: K -> fp16 natural, V -> fp16 transposed [d][s].
// prep_m: mask int32 -> bitpacked uint4 per 128 keys (word k&3, bit k>>2).
// Pass 1: sums (via ones-mma) + context: fp16 mma, ex2.approx.f16x2 exps.
// Pass 2: recompute scores, w = exp2f16(s*log2e*scale)*ri -> fp32 out.

#define SDIM    2048
#define DDIM    64
#define BHN     32
#define TQ      128
#define WQ      16
#define CK      64
#define NCH     32
#define KSTRH   88
#define VSTRH   88
#define THREADS 256
#define SCLOG2E 0.180336879f    // 0.125 * log2(e)
#define HONES   0x3C003C00u     // half2(1.0, 1.0)

#define SMEM_BYTES1 (22528 + 22528)
#define SMEM_BYTES2 (22528)

__device__ float    g_ri[BHN * SDIM];
__device__ __half   g_Kh [(size_t)BHN * SDIM * DDIM];
__device__ __half   g_Vt [(size_t)BHN * DDIM * SDIM];
__device__ uint4    g_Mp [(size_t)BHN * SDIM * (SDIM / 128)];

__device__ __forceinline__ uint32_t f22h(float x, float y) {
    __half2 h = __floats2half2_rn(x, y);
    return *(uint32_t*)&h;
}
__device__ __forceinline__ uint32_t hexp2x2(uint32_t x) {
    uint32_t r;
    asm("ex2.approx.f16x2 %0, %1;" : "=r"(r) : "r"(x));
    return r;
}

__device__ __forceinline__ void mma_f16(float c[4],
    uint32_t a0, uint32_t a1, uint32_t a2, uint32_t a3,
    uint32_t b0, uint32_t b1)
{
    asm volatile(
        "mma.sync.aligned.m16n8k16.row.col.f32.f16.f16.f32 "
        "{%0,%1,%2,%3}, {%4,%5,%6,%7}, {%8,%9}, {%0,%1,%2,%3};"
        : "+f"(c[0]), "+f"(c[1]), "+f"(c[2]), "+f"(c[3])
        : "r"(a0), "r"(a1), "r"(a2), "r"(a3), "r"(b0), "r"(b1));
}

#define LDSM_X4(r, addr) \
    asm volatile("ldmatrix.sync.aligned.m8n8.x4.shared.b16 {%0,%1,%2,%3}, [%4];" \
        : "=r"((r)[0]), "=r"((r)[1]), "=r"((r)[2]), "=r"((r)[3]) : "r"(addr))

__device__ __forceinline__ void cp16(void* dst_smem, const void* src) {
    uint32_t d = (uint32_t)__cvta_generic_to_shared(dst_smem);
    asm volatile("cp.async.cg.shared.global [%0], [%1], 16;" :: "r"(d), "l"(src));
}
__device__ __forceinline__ void stg_cs64(float* p, float2 v) {
    asm volatile("st.global.cs.v2.f32 [%0], {%1,%2};" :: "l"(p), "f"(v.x), "f"(v.y) : "memory");
}
#define CP_COMMIT()  asm volatile("cp.async.commit_group;" ::: "memory")
#define CP_WAIT0()   asm volatile("cp.async.wait_group 0;" ::: "memory")

// ---- prep: K fp32 -> fp16 natural ----
__global__ __launch_bounds__(256)
void prep_k(const float* __restrict__ K)
{
    size_t i = ((size_t)blockIdx.x * 256 + threadIdx.x) * 4;
    float4 v = *(const float4*)(K + i);
    __half2* o = (__half2*)(g_Kh + i);
    o[0] = __floats2half2_rn(v.x, v.y);
    o[1] = __floats2half2_rn(v.z, v.w);
}

// ---- prep: V fp32 [s][d] -> fp16 transposed [d][s] ----
__global__ __launch_bounds__(256)
void prep_v(const float* __restrict__ V)
{
    __shared__ float tile[64][65];
    const int bh = blockIdx.y, s0 = blockIdx.x * 64;
    const float* Vb = V + ((size_t)bh * SDIM + s0) * DDIM;
    const int t = threadIdx.x;
#pragma unroll
    for (int j = 0; j < 4; j++) {
        int i = t + 256 * j, r = i >> 4, c4 = i & 15;
        float4 v = *(const float4*)(Vb + (size_t)r * DDIM + c4 * 4);
        tile[r][c4 * 4 + 0] = v.x; tile[r][c4 * 4 + 1] = v.y;
        tile[r][c4 * 4 + 2] = v.z; tile[r][c4 * 4 + 3] = v.w;
    }
    __syncthreads();
    const int d = t >> 2, sb = (t & 3) * 16;
    __half2* o = (__half2*)(g_Vt + ((size_t)bh * DDIM + d) * SDIM + s0 + sb);
#pragma unroll
    for (int k = 0; k < 8; k++)
        o[k] = __floats2half2_rn(tile[sb + 2 * k][d], tile[sb + 2 * k + 1][d]);
}

// ---- prep: mask -> packed uint4 per 128 keys. key k: word k&3, bit k>>2 ----
__global__ __launch_bounds__(256)
void prep_m(const int* __restrict__ M)
{
    const int row  = (int)blockIdx.x * 8 + (int)(threadIdx.x >> 5);
    const int lane = threadIdx.x & 31;
    const int4* mr = (const int4*)(M + (size_t)row * SDIM);
    uint4* out = g_Mp + (size_t)row * 16;
#pragma unroll 4
    for (int it = 0; it < 16; it++) {
        int4 v = mr[it * 32 + lane];
        uint32_t nib = (v.x != 0) | ((v.y != 0) << 1)
                     | ((v.z != 0) << 2) | ((v.w != 0) << 3);
        uint32_t b0 = __ballot_sync(0xffffffffu, nib & 1);
        uint32_t b1 = __ballot_sync(0xffffffffu, nib & 2);
        uint32_t b2 = __ballot_sync(0xffffffffu, nib & 4);
        uint32_t b3 = __ballot_sync(0xffffffffu, nib & 8);
        if (lane == 0) out[it] = make_uint4(b0, b1, b2, b3);
    }
}

// =================== pass 1: row sums (ones-mma) + context ===================
__global__ __launch_bounds__(THREADS, 2)
void attn_pass1(const float* __restrict__ Q, float* __restrict__ ctx)
{
    extern __shared__ __half smh[];
    __half* Ksm = smh;                        // [2][64 x 88]
    __half* Vsm = smh + 2 * 64 * KSTRH;       // [2][64 x 88]

    const int t    = threadIdx.x;
    const int w    = t >> 5;
    const int lane = t & 31;
    const int grp  = lane >> 2;
    const int tig  = lane & 3;
    const int bh   = blockIdx.y;
    const int qw   = blockIdx.x * TQ + w * WQ;

    const __half* KhB = g_Kh + (size_t)bh * SDIM * DDIM;
    const __half* VtB = g_Vt + (size_t)bh * DDIM * SDIM;
    const float* Qw = Q + ((size_t)bh * SDIM + qw) * DDIM;
    const uint4* Mp0 = g_Mp + ((size_t)bh * SDIM + qw + grp) * 16;
    const uint4* Mp1 = Mp0 + 8 * 16;
    float* Cw = ctx + ((size_t)bh * SDIM + qw) * DDIM;

#pragma unroll
    for (int j = 0; j < 2; j++) {
        int i = t + THREADS * j, row = i >> 3, seg = i & 7;
        cp16(Ksm + row * KSTRH + seg * 8, KhB + (size_t)row * DDIM + seg * 8);
        cp16(Vsm + row * VSTRH + seg * 8, VtB + (size_t)row * SDIM + seg * 8);
    }
    CP_COMMIT();

    uint4 cm0 = Mp0[0], cm1 = Mp1[0];
    uint4 nx0, nx1;

    uint32_t aq[4][4];
#pragma unroll
    for (int kb = 0; kb < 4; kb++) {
        float2 q00 = *(const float2*)(Qw + (size_t)grp * DDIM + kb * 16 + 2 * tig);
        float2 q10 = *(const float2*)(Qw + (size_t)(grp + 8) * DDIM + kb * 16 + 2 * tig);
        float2 q01 = *(const float2*)(Qw + (size_t)grp * DDIM + kb * 16 + 2 * tig + 8);
        float2 q11 = *(const float2*)(Qw + (size_t)(grp + 8) * DDIM + kb * 16 + 2 * tig + 8);
        aq[kb][0] = f22h(q00.x, q00.y);
        aq[kb][1] = f22h(q10.x, q10.y);
        aq[kb][2] = f22h(q01.x, q01.y);
        aq[kb][3] = f22h(q11.x, q11.y);
    }

    const uint32_t kfo = ((lane & 7) * KSTRH + (lane >> 4) * 16 + ((lane >> 3) & 1) * 8) * 2;
    const uint32_t vfo = (((lane >> 4) * 8 + (lane & 7)) * VSTRH + ((lane >> 3) & 1) * 8) * 2;
    const uint32_t ksm0 = (uint32_t)__cvta_generic_to_shared(Ksm);
    const uint32_t vsm0 = (uint32_t)__cvta_generic_to_shared(Vsm);

    float scc[4] = {0.f, 0.f, 0.f, 0.f};     // row-sum accumulator (ones-mma)
    float cc[8][4];
#pragma unroll
    for (int dt = 0; dt < 8; dt++)
#pragma unroll
        for (int r = 0; r < 4; r++) cc[dt][r] = 0.f;

    const bool hiw  = tig & 1;
    const int  bitb = tig >> 1;

    for (int c = 0; c < NCH; c++) {
        CP_WAIT0();
        __syncthreads();
        const int par = c & 1;
        if (par == 0 && c + 2 < NCH) {
            nx0 = Mp0[(c >> 1) + 1];
            nx1 = Mp1[(c >> 1) + 1];
        }
        if (c + 1 < NCH) {
            __half* kd = Ksm + ((c + 1) & 1) * (64 * KSTRH);
            __half* vd = Vsm + ((c + 1) & 1) * (64 * VSTRH);
            const __half* ks = KhB + (size_t)(c + 1) * CK * DDIM;
            const __half* vs = VtB + (size_t)(c + 1) * CK;
#pragma unroll
            for (int j = 0; j < 2; j++) {
                int i = t + THREADS * j, row = i >> 3, seg = i & 7;
                cp16(kd + row * KSTRH + seg * 8, ks + (size_t)row * DDIM + seg * 8);
                cp16(vd + row * VSTRH + seg * 8, vs + (size_t)row * SDIM + seg * 8);
            }
            CP_COMMIT();
        }
        const uint32_t kbase = ksm0 + (c & 1) * (64 * KSTRH * 2) + kfo;
        const uint32_t vbase = vsm0 + (c & 1) * (64 * VSTRH * 2) + vfo;

        const uint32_t mwA0 = hiw ? cm0.z : cm0.x;
        const uint32_t mwB0 = hiw ? cm0.w : cm0.y;
        const uint32_t mwA1 = hiw ? cm1.z : cm1.x;
        const uint32_t mwB1 = hiw ? cm1.w : cm1.y;

#pragma unroll
        for (int s = 0; s < 2; s++) {
            float sa[4][4];
#pragma unroll
            for (int n2 = 0; n2 < 4; n2++) {
                const int nt = s * 4 + n2;
                const uint32_t ka = kbase + nt * (8 * KSTRH * 2);
                uint32_t b01[4], b23[4];
                LDSM_X4(b01, ka);
                LDSM_X4(b23, ka + 64);
                float acc[4] = {0.f, 0.f, 0.f, 0.f};
                mma_f16(acc, aq[0][0], aq[0][1], aq[0][2], aq[0][3], b01[0], b01[1]);
                mma_f16(acc, aq[1][0], aq[1][1], aq[1][2], aq[1][3], b01[2], b01[3]);
                mma_f16(acc, aq[2][0], aq[2][1], aq[2][2], aq[2][3], b23[0], b23[1]);
                mma_f16(acc, aq[3][0], aq[3][1], aq[3][2], aq[3][3], b23[2], b23[3]);
                sa[n2][0] = acc[0]; sa[n2][1] = acc[1];
                sa[n2][2] = acc[2]; sa[n2][3] = acc[3];
            }

            // ---- exp via ex2.approx.f16x2 (2 exps / MUFU op) ----
            uint32_t eL[4], eH[4];
#pragma unroll
            for (int n2 = 0; n2 < 4; n2++) {
                const int bit = par * 16 + s * 8 + n2 * 2 + bitb;
                float x00 = (mwA0 >> bit) & 1 ? -100.f : sa[n2][0] * SCLOG2E;
                float x01 = (mwB0 >> bit) & 1 ? -100.f : sa[n2][1] * SCLOG2E;
                float x10 = (mwA1 >> bit) & 1 ? -100.f : sa[n2][2] * SCLOG2E;
                float x11 = (mwB1 >> bit) & 1 ? -100.f : sa[n2][3] * SCLOG2E;
                eL[n2] = hexp2x2(f22h(x00, x01));
                eH[n2] = hexp2x2(f22h(x10, x11));
            }

            // ---- context + row sums (extra ones-mma per k16 group) ----
#pragma unroll
            for (int g = 0; g < 2; g++) {
                const uint32_t a0 = eL[2 * g], a2 = eL[2 * g + 1];
                const uint32_t a1 = eH[2 * g], a3 = eH[2 * g + 1];
                const uint32_t off = (s * 32 + g * 16) * 2;
                mma_f16(scc, a0, a1, a2, a3, HONES, HONES);
#pragma unroll
                for (int dtp = 0; dtp < 4; dtp++) {
                    uint32_t vb[4];
                    LDSM_X4(vb, vbase + dtp * (16 * VSTRH * 2) + off);
                    mma_f16(cc[2 * dtp],     a0, a1, a2, a3, vb[0], vb[1]);
                    mma_f16(cc[2 * dtp + 1], a0, a1, a2, a3, vb[2], vb[3]);
                }
            }
        }
        if (par == 1) { cm0 = nx0; cm1 = nx1; }
    }

    // scc[0] / scc[2] already hold the COMPLETE row sums (ones-mma)
    const float ri0 = 1.0f / scc[0], ri1 = 1.0f / scc[2];
    if (tig == 0) {
        g_ri[(size_t)bh * SDIM + qw + grp]     = ri0;
        g_ri[(size_t)bh * SDIM + qw + grp + 8] = ri1;
    }
#pragma unroll
    for (int dt = 0; dt < 8; dt++) {
        *(float2*)(Cw + (size_t)grp * DDIM + dt * 8 + tig * 2) =
            make_float2(cc[dt][0] * ri0, cc[dt][1] * ri0);
        *(float2*)(Cw + (size_t)(grp + 8) * DDIM + dt * 8 + tig * 2) =
            make_float2(cc[dt][2] * ri1, cc[dt][3] * ri1);
    }
}

// ========= pass 2: recompute scores, w = exp2f16 * ri -> fp32 weights =========
__global__ __launch_bounds__(THREADS, 3)
void attn_pass2(const float* __restrict__ Q, float* __restrict__ wout)
{
    extern __shared__ __half smh[];
    __half* Ksm = smh;                        // [2][64 x 88]

    const int t    = threadIdx.x;
    const int lane = t & 31;
    const int w    = t >> 5;
    const int grp  = lane >> 2;
    const int tig  = lane & 3;
    const int bh   = blockIdx.y;
    const int qw   = blockIdx.x * TQ + w * WQ;

    const __half* KhB = g_Kh + (size_t)bh * SDIM * DDIM;
    const float* Qw = Q + ((size_t)bh * SDIM + qw) * DDIM;
    const uint4* Mp0 = g_Mp + ((size_t)bh * SDIM + qw + grp) * 16;
    const uint4* Mp1 = Mp0 + 8 * 16;
    float* Wo = wout + ((size_t)bh * SDIM + qw) * SDIM;

    const float ri0 = g_ri[(size_t)bh * SDIM + qw + grp];
    const float ri1 = g_ri[(size_t)bh * SDIM + qw + grp + 8];

#pragma unroll
    for (int j = 0; j < 2; j++) {
        int i = t + THREADS * j, row = i >> 3, seg = i & 7;
        cp16(Ksm + row * KSTRH + seg * 8, KhB + (size_t)row * DDIM + seg * 8);
    }
    CP_COMMIT();

    uint4 cm0 = Mp0[0], cm1 = Mp1[0];
    uint4 nx0, nx1;

    uint32_t aq[4][4];
#pragma unroll
    for (int kb = 0; kb < 4; kb++) {
        float2 q00 = *(const float2*)(Qw + (size_t)grp * DDIM + kb * 16 + 2 * tig);
        float2 q10 = *(const float2*)(Qw + (size_t)(grp + 8) * DDIM + kb * 16 + 2 * tig);
        float2 q01 = *(const float2*)(Qw + (size_t)grp * DDIM + kb * 16 + 2 * tig + 8);
        float2 q11 = *(const float2*)(Qw + (size_t)(grp + 8) * DDIM + kb * 16 + 2 * tig + 8);
        aq[kb][0] = f22h(q00.x, q00.y);
        aq[kb][1] = f22h(q10.x, q10.y);
        aq[kb][2] = f22h(q01.x, q01.y);
        aq[kb][3] = f22h(q11.x, q11.y);
    }

    const uint32_t kfo = ((lane & 7) * KSTRH + (lane >> 4) * 16 + ((lane >> 3) & 1) * 8) * 2;
    const uint32_t ksm0 = (uint32_t)__cvta_generic_to_shared(Ksm);
    const bool hiw  = tig & 1;
    const int  bitb = tig >> 1;

    for (int c = 0; c < NCH; c++) {
        CP_WAIT0();
        __syncthreads();
        const int par = c & 1;
        if (par == 0 && c + 2 < NCH) {
            nx0 = Mp0[(c >> 1) + 1];
            nx1 = Mp1[(c >> 1) + 1];
        }
        if (c + 1 < NCH) {
            __half* kd = Ksm + ((c + 1) & 1) * (64 * KSTRH);
            const __half* ks = KhB + (size_t)(c + 1) * CK * DDIM;
#pragma unroll
            for (int j = 0; j < 2; j++) {
                int i = t + THREADS * j, row = i >> 3, seg = i & 7;
                cp16(kd + row * KSTRH + seg * 8, ks + (size_t)row * DDIM + seg * 8);
            }
            CP_COMMIT();
        }
        const uint32_t kbase = ksm0 + (c & 1) * (64 * KSTRH * 2) + kfo;

        const uint32_t mwA0 = hiw ? cm0.z : cm0.x;
        const uint32_t mwB0 = hiw ? cm0.w : cm0.y;
        const uint32_t mwA1 = hiw ? cm1.z : cm1.x;
        const uint32_t mwB1 = hiw ? cm1.w : cm1.y;

#pragma unroll
        for (int s = 0; s < 2; s++) {
            float sa[4][4];
#pragma unroll
            for (int n2 = 0; n2 < 4; n2++) {
                const int nt = s * 4 + n2;
                const uint32_t ka = kbase + nt * (8 * KSTRH * 2);
                uint32_t b01[4], b23[4];
                LDSM_X4(b01, ka);
                LDSM_X4(b23, ka + 64);
                float acc[4] = {0.f, 0.f, 0.f, 0.f};
                mma_f16(acc, aq[0][0], aq[0][1], aq[0][2], aq[0][3], b01[0], b01[1]);
                mma_f16(acc, aq[1][0], aq[1][1], aq[1][2], aq[1][3], b01[2], b01[3]);
                mma_f16(acc, aq[2][0], aq[2][1], aq[2][2], aq[2][3], b23[0], b23[1]);
                mma_f16(acc, aq[3][0], aq[3][1], aq[3][2], aq[3][3], b23[2], b23[3]);
                sa[n2][0] = acc[0]; sa[n2][1] = acc[1];
                sa[n2][2] = acc[2]; sa[n2][3] = acc[3];
            }

#pragma unroll
            for (int n2 = 0; n2 < 4; n2++) {
                const int nt  = s * 4 + n2;
                const int bit = par * 16 + s * 8 + n2 * 2 + bitb;
                float x00 = (mwA0 >> bit) & 1 ? -100.f : sa[n2][0] * SCLOG2E;
                float x01 = (mwB0 >> bit) & 1 ? -100.f : sa[n2][1] * SCLOG2E;
                float x10 = (mwA1 >> bit) & 1 ? -100.f : sa[n2][2] * SCLOG2E;
                float x11 = (mwB1 >> bit) & 1 ? -100.f : sa[n2][3] * SCLOG2E;
                uint32_t p0 = hexp2x2(f22h(x00, x01));
                uint32_t p1 = hexp2x2(f22h(x10, x11));
                float2 f0 = __half22float2(*(const __half2*)&p0);
                float2 f1 = __half22float2(*(const __half2*)&p1);
                stg_cs64(Wo + (size_t)grp * SDIM + c * CK + nt * 8 + tig * 2,
                         make_float2(f0.x * ri0, f0.y * ri0));
                stg_cs64(Wo + (size_t)(grp + 8) * SDIM + c * CK + nt * 8 + tig * 2,
                         make_float2(f1.x * ri1, f1.y * ri1));
            }
        }
        if (par == 1) { cm0 = nx0; cm1 = nx1; }
    }
}

extern "C" void kernel_launch(void* const* d_in, const int* in_sizes, int n_in,
                              void* d_out, int out_size)
{
    const float* Q = (const float*)d_in[0];
    const float* K = (const float*)d_in[1];
    const float* V = (const float*)d_in[2];
    const int*   M = (const int*)d_in[3];

    float* ctx  = (float*)d_out;
    float* wout = (float*)d_out + (size_t)BHN * SDIM * DDIM;

    prep_k<<<(BHN * SDIM * DDIM) / (256 * 4), 256>>>(K);
    prep_v<<<dim3(SDIM / 64, BHN), 256>>>(V);
    prep_m<<<(BHN * SDIM) / 8, 256>>>(M);

    cudaFuncSetAttribute(attn_pass1,
                         cudaFuncAttributeMaxDynamicSharedMemorySize, SMEM_BYTES1);
    cudaFuncSetAttribute(attn_pass2,
                         cudaFuncAttributeMaxDynamicSharedMemorySize, SMEM_BYTES2);

    dim3 grid(SDIM / TQ, BHN);
    attn_pass1<<<grid, THREADS, SMEM_BYTES1>>>(Q, ctx);
    attn_pass2<<<grid, THREADS, SMEM_BYTES2>>>(Q, wout);
}